// round 1
// baseline (speedup 1.0000x reference)
#include <cuda_runtime.h>
#include <cstdint>
#include <cstddef>

#define N_NODES 100000
#define N_EDGES 1600000
#define N_LBL   200000
#define DIM_IN  256
#define DIM_H1  128
#define DIM_H   64
#define DIM_EA  8

// ---------------- scratch (no allocations allowed) ----------------
__device__ __align__(16) float g_h1[(size_t)N_NODES * DIM_H1];
__device__ __align__(16) float g_h [(size_t)N_NODES * DIM_H];
__device__ __align__(16) float g_xw[(size_t)N_NODES * DIM_H];
__device__ __align__(16) float g_agg[(size_t)N_NODES * DIM_H];
__device__ int   g_row[N_EDGES];
__device__ int   g_col[N_EDGES];
__device__ int   g_src[N_LBL];
__device__ int   g_dst[N_LBL];
__device__ int   g_deg[N_NODES];
__device__ float g_dinv[N_NODES];   // rsqrt(deg)
__device__ float g_dinv2[N_NODES];  // 1/deg
__device__ int   g_flag[2];         // [0]=edge_index is int64, [1]=edge_label_index is int64

__device__ __forceinline__ float leaky(float v) {
    return v > 0.0f ? v : 0.01f * v;
}

// ---------------- dtype detection ----------------
// If the raw buffer is int64 (values < 2^31), every odd 32-bit word is 0.
__global__ void detect64_kernel(const int* __restrict__ p, int flag_slot) {
    __shared__ int anynz;
    if (threadIdx.x == 0) anynz = 0;
    __syncthreads();
    for (int i = threadIdx.x; i < 2048; i += blockDim.x) {
        if (p[2 * i + 1] != 0) anynz = 1;
    }
    __syncthreads();
    if (threadIdx.x == 0) g_flag[flag_slot] = (anynz == 0) ? 1 : 0;
}

__global__ void zero_deg_kernel() {
    int i = blockIdx.x * blockDim.x + threadIdx.x;
    if (i < N_NODES) g_deg[i] = 0;
}

__global__ void convert_edges_kernel(const void* __restrict__ raw) {
    int e = blockIdx.x * blockDim.x + threadIdx.x;
    if (e >= N_EDGES) return;
    int r, c;
    if (g_flag[0]) {
        const long long* p = (const long long*)raw;
        r = (int)p[e];
        c = (int)p[N_EDGES + e];
    } else {
        const int* p = (const int*)raw;
        r = p[e];
        c = p[N_EDGES + e];
    }
    g_row[e] = r;
    g_col[e] = c;
    atomicAdd(&g_deg[c], 1);
}

__global__ void convert_label_kernel(const void* __restrict__ raw) {
    int e = blockIdx.x * blockDim.x + threadIdx.x;
    if (e >= N_LBL) return;
    int s, d;
    if (g_flag[1]) {
        const long long* p = (const long long*)raw;
        s = (int)p[e];
        d = (int)p[N_LBL + e];
    } else {
        const int* p = (const int*)raw;
        s = p[e];
        d = p[N_LBL + e];
    }
    g_src[e] = s;
    g_dst[e] = d;
}

__global__ void deg_finalize_kernel() {
    int i = blockIdx.x * blockDim.x + threadIdx.x;
    if (i >= N_NODES) return;
    float fd = (float)(g_deg[i] + 1);  // +1 self loop
    g_dinv[i]  = rsqrtf(fd);
    g_dinv2[i] = 1.0f / fd;
}

// ---------------- tiled fp32 GEMM: C = act(A[M,K] @ B[K,N] + bias) ----------------
template<int BM, int BN, int BK, int TM, int TN, bool BIAS, bool ACT>
__global__ void gemm_kernel(const float* __restrict__ A, const float* __restrict__ B,
                            const float* __restrict__ bias, float* __restrict__ C,
                            int M, int N, int K) {
    constexpr int THREADS = (BM / TM) * (BN / TN);
    __shared__ float As[BK][BM];
    __shared__ float Bs[BK][BN];

    const int tid = threadIdx.x;
    const int tx = tid % (BN / TN);
    const int ty = tid / (BN / TN);
    const int row0 = blockIdx.y * BM;
    const int col0 = blockIdx.x * BN;

    float acc[TM][TN];
#pragma unroll
    for (int i = 0; i < TM; i++)
#pragma unroll
        for (int j = 0; j < TN; j++) acc[i][j] = 0.0f;

    constexpr int A_LOADS = (BM * BK) / (THREADS * 4);
    constexpr int B_LOADS = (BK * BN) / (THREADS * 4);

    for (int k0 = 0; k0 < K; k0 += BK) {
#pragma unroll
        for (int i = 0; i < A_LOADS; i++) {
            int elem = (tid + i * THREADS) * 4;
            int r = elem / BK, c = elem % BK;
            float4 v = make_float4(0.f, 0.f, 0.f, 0.f);
            if (row0 + r < M)
                v = *(const float4*)(A + (size_t)(row0 + r) * K + k0 + c);
            As[c + 0][r] = v.x;
            As[c + 1][r] = v.y;
            As[c + 2][r] = v.z;
            As[c + 3][r] = v.w;
        }
#pragma unroll
        for (int i = 0; i < B_LOADS; i++) {
            int elem = (tid + i * THREADS) * 4;
            int r = elem / BN, c = elem % BN;
            *(float4*)&Bs[r][c] = *(const float4*)(B + (size_t)(k0 + r) * N + col0 + c);
        }
        __syncthreads();
#pragma unroll
        for (int k = 0; k < BK; k++) {
            float a[TM], b[TN];
#pragma unroll
            for (int i = 0; i < TM; i++) a[i] = As[k][ty * TM + i];
#pragma unroll
            for (int j = 0; j < TN; j++) b[j] = Bs[k][tx * TN + j];
#pragma unroll
            for (int i = 0; i < TM; i++)
#pragma unroll
                for (int j = 0; j < TN; j++) acc[i][j] = fmaf(a[i], b[j], acc[i][j]);
        }
        __syncthreads();
    }

#pragma unroll
    for (int i = 0; i < TM; i++) {
        int r = row0 + ty * TM + i;
        if (r >= M) continue;
#pragma unroll
        for (int j = 0; j < TN; j++) {
            int c = col0 + tx * TN + j;
            float v = acc[i][j];
            if (BIAS) v += bias[c];
            if (ACT) v = leaky(v);
            C[(size_t)r * N + c] = v;
        }
    }
}

// ---------------- GCN aggregation ----------------
// agg[i] = xw[i] * (1/deg[i])   (self-loop term; also serves as zero-init)
__global__ void init_agg_kernel() {
    int i = blockIdx.x * blockDim.x + threadIdx.x;
    if (i >= N_NODES * (DIM_H / 4)) return;
    int node = i >> 4;
    float s = g_dinv2[node];
    float4 v = ((const float4*)g_xw)[i];
    v.x *= s; v.y *= s; v.z *= s; v.w *= s;
    ((float4*)g_agg)[i] = v;
}

// agg[col] += dinv[row]*dinv[col] * xw[row]   — 16 lanes per edge, float4 each
__global__ void scatter_kernel() {
    long long it = (long long)blockIdx.x * blockDim.x + threadIdx.x;
    int e = (int)(it >> 4);
    int c = (int)(it & 15);
    if (e >= N_EDGES) return;
    int r = g_row[e], cl = g_col[e];
    float nrm = g_dinv[r] * g_dinv[cl];
    float4 v = ((const float4*)(g_xw + (size_t)r * DIM_H))[c];
    v.x *= nrm; v.y *= nrm; v.z *= nrm; v.w *= nrm;
    float* dst = g_agg + (size_t)cl * DIM_H + c * 4;
    asm volatile("red.global.add.v4.f32 [%0], {%1, %2, %3, %4};"
                 :: "l"(dst), "f"(v.x), "f"(v.y), "f"(v.z), "f"(v.w)
                 : "memory");
}

// h = leaky(agg + b)
__global__ void gcn_epilogue_kernel(const float* __restrict__ bias, float* __restrict__ hdst) {
    int i = blockIdx.x * blockDim.x + threadIdx.x;
    if (i >= N_NODES * (DIM_H / 4)) return;
    float4 v = ((const float4*)g_agg)[i];
    int j = (i & 15) * 4;
    v.x = leaky(v.x + bias[j + 0]);
    v.y = leaky(v.y + bias[j + 1]);
    v.z = leaky(v.z + bias[j + 2]);
    v.w = leaky(v.w + bias[j + 3]);
    ((float4*)hdst)[i] = v;
}

// ---------------- edge scoring head: one warp per label edge ----------------
__global__ void edge_score_kernel(const float* __restrict__ h,
                                  const float* __restrict__ ea,
                                  const float* __restrict__ Wp,
                                  const float* __restrict__ bp,
                                  float* __restrict__ out) {
    int warp = (blockIdx.x * blockDim.x + threadIdx.x) >> 5;
    int lane = threadIdx.x & 31;
    if (warp >= N_LBL) return;
    int s = g_src[warp], d = g_dst[warp];
    const float* hs = h + (size_t)s * DIM_H;
    const float* hd = h + (size_t)d * DIM_H;
    float acc = hs[lane]      * __ldg(&Wp[lane])
              + hs[lane + 32] * __ldg(&Wp[lane + 32])
              + hd[lane]      * __ldg(&Wp[64 + lane])
              + hd[lane + 32] * __ldg(&Wp[96 + lane]);
    if (lane < DIM_EA)
        acc += ea[(size_t)warp * DIM_EA + lane] * __ldg(&Wp[128 + lane]);
#pragma unroll
    for (int o = 16; o; o >>= 1) acc += __shfl_xor_sync(0xffffffffu, acc, o);
    if (lane == 0) out[warp] = acc + __ldg(&bp[0]);
}

// ---------------- host ----------------
static void* sym_addr(const void* sym) {
    void* p = nullptr;
    cudaGetSymbolAddress(&p, sym);
    return p;
}

extern "C" void kernel_launch(void* const* d_in, const int* in_sizes, int n_in,
                              void* d_out, int out_size) {
    const float* x   = (const float*)d_in[0];
    const void*  ei  = d_in[1];
    const void*  eli = d_in[2];
    const float* ea  = (const float*)d_in[3];
    const float* W1  = (const float*)d_in[4];
    const float* b1  = (const float*)d_in[5];
    const float* W2  = (const float*)d_in[6];
    const float* b2  = (const float*)d_in[7];
    const float* Wg1 = (const float*)d_in[8];
    const float* bg1 = (const float*)d_in[9];
    const float* Wg2 = (const float*)d_in[10];
    const float* bg2 = (const float*)d_in[11];
    const float* Wp  = (const float*)d_in[12];
    const float* bp  = (const float*)d_in[13];

    float* out  = (float*)d_out;
    float* hout = out + N_LBL;

    float* h1  = (float*)sym_addr(g_h1);
    float* h   = (float*)sym_addr(g_h);
    float* xw  = (float*)sym_addr(g_xw);

    // --- index preprocessing ---
    zero_deg_kernel<<<(N_NODES + 255) / 256, 256>>>();
    detect64_kernel<<<1, 128>>>((const int*)ei, 0);
    detect64_kernel<<<1, 128>>>((const int*)eli, 1);
    convert_edges_kernel<<<(N_EDGES + 255) / 256, 256>>>(ei);
    convert_label_kernel<<<(N_LBL + 255) / 256, 256>>>(eli);
    deg_finalize_kernel<<<(N_NODES + 255) / 256, 256>>>();

    // --- preprocess MLP ---
    {
        dim3 g(DIM_H1 / 128, (N_NODES + 127) / 128);
        gemm_kernel<128, 128, 16, 8, 8, true, true><<<g, 256>>>(x, W1, b1, h1, N_NODES, DIM_H1, DIM_IN);
    }
    {
        dim3 g(DIM_H / 64, (N_NODES + 127) / 128);
        gemm_kernel<128, 64, 16, 8, 4, true, true><<<g, 256>>>(h1, W2, b2, h, N_NODES, DIM_H, DIM_H1);
    }

    const int n16 = N_NODES * (DIM_H / 4);
    const long long scat_items = (long long)N_EDGES * 16;
    const int scat_blocks = (int)((scat_items + 255) / 256);

    // --- GCN layer 1 ---
    {
        dim3 g(DIM_H / 64, (N_NODES + 127) / 128);
        gemm_kernel<128, 64, 16, 8, 4, false, false><<<g, 256>>>(h, Wg1, nullptr, xw, N_NODES, DIM_H, DIM_H);
    }
    init_agg_kernel<<<(n16 + 255) / 256, 256>>>();
    scatter_kernel<<<scat_blocks, 256>>>();
    gcn_epilogue_kernel<<<(n16 + 255) / 256, 256>>>(bg1, h);

    // --- GCN layer 2 ---
    {
        dim3 g(DIM_H / 64, (N_NODES + 127) / 128);
        gemm_kernel<128, 64, 16, 8, 4, false, false><<<g, 256>>>(h, Wg2, nullptr, xw, N_NODES, DIM_H, DIM_H);
    }
    init_agg_kernel<<<(n16 + 255) / 256, 256>>>();
    scatter_kernel<<<scat_blocks, 256>>>();
    gcn_epilogue_kernel<<<(n16 + 255) / 256, 256>>>(bg2, hout);

    // --- edge scoring head ---
    edge_score_kernel<<<(N_LBL * 32 + 255) / 256, 256>>>(hout, ea, Wp, bp, out);
}

// round 2
// speedup vs baseline: 1.2158x; 1.2158x over previous
#include <cuda_runtime.h>
#include <cstdint>
#include <cstddef>

#define N_NODES 100000
#define N_EDGES 1600000
#define N_LBL   200000
#define DIM_IN  256
#define DIM_H1  128
#define DIM_H   64
#define DIM_EA  8

#define SCAN_TPB    512
#define SCAN_BLOCKS ((N_NODES + SCAN_TPB - 1) / SCAN_TPB)   // 196

// ---------------- scratch (no allocations allowed) ----------------
__device__ __align__(16) float g_h1[(size_t)N_NODES * DIM_H1];
__device__ __align__(16) float g_h [(size_t)N_NODES * DIM_H];
__device__ __align__(16) float g_xw[(size_t)N_NODES * DIM_H];
__device__ int   g_row[N_EDGES];
__device__ int   g_col[N_EDGES];
__device__ int   g_perm[N_EDGES];       // CSR: source row per incoming edge, bucketed by col
__device__ int   g_src[N_LBL];
__device__ int   g_dst[N_LBL];
__device__ int   g_deg[N_NODES];
__device__ int   g_start[N_NODES + 1];  // CSR offsets
__device__ int   g_cursor[N_NODES];
__device__ int   g_part[SCAN_BLOCKS];
__device__ float g_dinv[N_NODES];       // rsqrt(deg+1)
__device__ float g_dinv2[N_NODES];      // 1/(deg+1)
__device__ int   g_flag[2];             // [0]=edge_index is int64, [1]=edge_label_index is int64

__device__ __forceinline__ float leaky(float v) {
    return v > 0.0f ? v : 0.01f * v;
}

// ---------------- dtype detection ----------------
__global__ void detect64_kernel(const int* __restrict__ p, int flag_slot) {
    __shared__ int anynz;
    if (threadIdx.x == 0) anynz = 0;
    __syncthreads();
    for (int i = threadIdx.x; i < 2048; i += blockDim.x) {
        if (p[2 * i + 1] != 0) anynz = 1;
    }
    __syncthreads();
    if (threadIdx.x == 0) g_flag[flag_slot] = (anynz == 0) ? 1 : 0;
}

__global__ void zero_deg_kernel() {
    int i = blockIdx.x * blockDim.x + threadIdx.x;
    if (i < N_NODES) g_deg[i] = 0;
}

__global__ void convert_edges_kernel(const void* __restrict__ raw) {
    int e = blockIdx.x * blockDim.x + threadIdx.x;
    if (e >= N_EDGES) return;
    int r, c;
    if (g_flag[0]) {
        const long long* p = (const long long*)raw;
        r = (int)p[e];
        c = (int)p[N_EDGES + e];
    } else {
        const int* p = (const int*)raw;
        r = p[e];
        c = p[N_EDGES + e];
    }
    g_row[e] = r;
    g_col[e] = c;
    atomicAdd(&g_deg[c], 1);
}

__global__ void convert_label_kernel(const void* __restrict__ raw) {
    int e = blockIdx.x * blockDim.x + threadIdx.x;
    if (e >= N_LBL) return;
    if (g_flag[1]) {
        const long long* p = (const long long*)raw;
        g_src[e] = (int)p[e];
        g_dst[e] = (int)p[N_LBL + e];
    } else {
        const int* p = (const int*)raw;
        g_src[e] = p[e];
        g_dst[e] = p[N_LBL + e];
    }
}

// ---------------- CSR build: 3-phase prefix scan over deg ----------------
__global__ void scan_partials_kernel() {
    __shared__ int sh[SCAN_TPB];
    int t = threadIdx.x;
    int i = blockIdx.x * SCAN_TPB + t;
    int v = (i < N_NODES) ? g_deg[i] : 0;
    sh[t] = v;
    __syncthreads();
    for (int off = SCAN_TPB / 2; off > 0; off >>= 1) {
        if (t < off) sh[t] += sh[t + off];
        __syncthreads();
    }
    if (t == 0) g_part[blockIdx.x] = sh[0];
}

__global__ void scan_top_kernel() {   // 1 block, 256 threads, scans SCAN_BLOCKS partials
    __shared__ int sh[256];
    int t = threadIdx.x;
    int v = (t < SCAN_BLOCKS) ? g_part[t] : 0;
    sh[t] = v;
    __syncthreads();
    for (int off = 1; off < 256; off <<= 1) {
        int x = (t >= off) ? sh[t - off] : 0;
        __syncthreads();
        sh[t] += x;
        __syncthreads();
    }
    if (t < SCAN_BLOCKS) g_part[t] = sh[t] - v;   // exclusive
}

__global__ void scan_final_kernel() {
    __shared__ int sh[SCAN_TPB];
    int t = threadIdx.x;
    int i = blockIdx.x * SCAN_TPB + t;
    int v = (i < N_NODES) ? g_deg[i] : 0;
    sh[t] = v;
    __syncthreads();
    for (int off = 1; off < SCAN_TPB; off <<= 1) {
        int x = (t >= off) ? sh[t - off] : 0;
        __syncthreads();
        sh[t] += x;
        __syncthreads();
    }
    if (i < N_NODES) {
        int excl = g_part[blockIdx.x] + sh[t] - v;
        g_start[i]  = excl;
        g_cursor[i] = excl;
        float fd = (float)(v + 1);           // +1 self loop
        g_dinv[i]  = rsqrtf(fd);
        g_dinv2[i] = 1.0f / fd;
    }
    if (i == 0) g_start[N_NODES] = N_EDGES;
}

__global__ void bucket_fill_kernel() {
    int e = blockIdx.x * blockDim.x + threadIdx.x;
    if (e >= N_EDGES) return;
    int c = g_col[e];
    int pos = atomicAdd(&g_cursor[c], 1);
    g_perm[pos] = g_row[e];
}

// ---------------- tiled fp32 GEMM: C = act(A[M,K] @ B[K,N] + bias) ----------------
template<int BM, int BN, int BK, int TM, int TN, bool BIAS, bool ACT>
__global__ void gemm_kernel(const float* __restrict__ A, const float* __restrict__ B,
                            const float* __restrict__ bias, float* __restrict__ C,
                            int M, int N, int K) {
    constexpr int THREADS = (BM / TM) * (BN / TN);
    __shared__ float As[BK][BM];
    __shared__ float Bs[BK][BN];

    const int tid = threadIdx.x;
    const int tx = tid % (BN / TN);
    const int ty = tid / (BN / TN);
    const int row0 = blockIdx.y * BM;
    const int col0 = blockIdx.x * BN;

    float acc[TM][TN];
#pragma unroll
    for (int i = 0; i < TM; i++)
#pragma unroll
        for (int j = 0; j < TN; j++) acc[i][j] = 0.0f;

    constexpr int A_LOADS = (BM * BK) / (THREADS * 4);
    constexpr int B_LOADS = (BK * BN) / (THREADS * 4);

    for (int k0 = 0; k0 < K; k0 += BK) {
#pragma unroll
        for (int i = 0; i < A_LOADS; i++) {
            int elem = (tid + i * THREADS) * 4;
            int r = elem / BK, c = elem % BK;
            float4 v = make_float4(0.f, 0.f, 0.f, 0.f);
            if (row0 + r < M)
                v = *(const float4*)(A + (size_t)(row0 + r) * K + k0 + c);
            As[c + 0][r] = v.x;
            As[c + 1][r] = v.y;
            As[c + 2][r] = v.z;
            As[c + 3][r] = v.w;
        }
#pragma unroll
        for (int i = 0; i < B_LOADS; i++) {
            int elem = (tid + i * THREADS) * 4;
            int r = elem / BN, c = elem % BN;
            *(float4*)&Bs[r][c] = *(const float4*)(B + (size_t)(k0 + r) * N + col0 + c);
        }
        __syncthreads();
#pragma unroll
        for (int k = 0; k < BK; k++) {
            float a[TM], b[TN];
#pragma unroll
            for (int i = 0; i < TM; i++) a[i] = As[k][ty * TM + i];
#pragma unroll
            for (int j = 0; j < TN; j++) b[j] = Bs[k][tx * TN + j];
#pragma unroll
            for (int i = 0; i < TM; i++)
#pragma unroll
                for (int j = 0; j < TN; j++) acc[i][j] = fmaf(a[i], b[j], acc[i][j]);
        }
        __syncthreads();
    }

#pragma unroll
    for (int i = 0; i < TM; i++) {
        int r = row0 + ty * TM + i;
        if (r >= M) continue;
#pragma unroll
        for (int j = 0; j < TN; j++) {
            int c = col0 + tx * TN + j;
            float v = acc[i][j];
            if (BIAS) v += bias[c];
            if (ACT) v = leaky(v);
            C[(size_t)r * N + c] = v;
        }
    }
}

// ---------------- fused GCN aggregation: one warp per destination node ----------------
// h[node] = leaky( sum_{e in CSR(node)} dinv[row]*dinv[node]*xw[row]
//                  + dinv2[node]*xw[node] + bias )
__global__ void gcn_agg_kernel(const float* __restrict__ xw,
                               const float* __restrict__ bias,
                               float* __restrict__ hdst) {
    int node = blockIdx.x * (blockDim.x >> 5) + (threadIdx.x >> 5);
    int lane = threadIdx.x & 31;
    if (node >= N_NODES) return;

    int s   = g_start[node];
    int end = g_start[node + 1];
    float dcol = g_dinv[node];

    float a0 = 0.0f, a1 = 0.0f;
    int j = s;
    for (; j + 2 <= end; j += 2) {
        int r0 = g_perm[j];
        int r1 = g_perm[j + 1];
        float w0 = g_dinv[r0] * dcol;
        float w1 = g_dinv[r1] * dcol;
        const float* p0 = xw + (size_t)r0 * DIM_H;
        const float* p1 = xw + (size_t)r1 * DIM_H;
        float v00 = p0[lane], v01 = p0[lane + 32];
        float v10 = p1[lane], v11 = p1[lane + 32];
        a0 = fmaf(w0, v00, a0);
        a1 = fmaf(w0, v01, a1);
        a0 = fmaf(w1, v10, a0);
        a1 = fmaf(w1, v11, a1);
    }
    if (j < end) {
        int r0 = g_perm[j];
        float w0 = g_dinv[r0] * dcol;
        const float* p0 = xw + (size_t)r0 * DIM_H;
        a0 = fmaf(w0, p0[lane], a0);
        a1 = fmaf(w0, p0[lane + 32], a1);
    }
    // self-loop
    float sw = g_dinv2[node];
    const float* ps = xw + (size_t)node * DIM_H;
    a0 = fmaf(sw, ps[lane], a0);
    a1 = fmaf(sw, ps[lane + 32], a1);

    a0 = leaky(a0 + bias[lane]);
    a1 = leaky(a1 + bias[lane + 32]);
    float* pd = hdst + (size_t)node * DIM_H;
    pd[lane]      = a0;
    pd[lane + 32] = a1;
}

// ---------------- edge scoring head: one warp per label edge ----------------
__global__ void edge_score_kernel(const float* __restrict__ h,
                                  const float* __restrict__ ea,
                                  const float* __restrict__ Wp,
                                  const float* __restrict__ bp,
                                  float* __restrict__ out) {
    int warp = (blockIdx.x * blockDim.x + threadIdx.x) >> 5;
    int lane = threadIdx.x & 31;
    if (warp >= N_LBL) return;
    int s = g_src[warp], d = g_dst[warp];
    const float* hs = h + (size_t)s * DIM_H;
    const float* hd = h + (size_t)d * DIM_H;
    float acc = hs[lane]      * __ldg(&Wp[lane])
              + hs[lane + 32] * __ldg(&Wp[lane + 32])
              + hd[lane]      * __ldg(&Wp[64 + lane])
              + hd[lane + 32] * __ldg(&Wp[96 + lane]);
    if (lane < DIM_EA)
        acc += ea[(size_t)warp * DIM_EA + lane] * __ldg(&Wp[128 + lane]);
#pragma unroll
    for (int o = 16; o; o >>= 1) acc += __shfl_xor_sync(0xffffffffu, acc, o);
    if (lane == 0) out[warp] = acc + __ldg(&bp[0]);
}

// ---------------- host ----------------
static void* sym_addr(const void* sym) {
    void* p = nullptr;
    cudaGetSymbolAddress(&p, sym);
    return p;
}

extern "C" void kernel_launch(void* const* d_in, const int* in_sizes, int n_in,
                              void* d_out, int out_size) {
    const float* x   = (const float*)d_in[0];
    const void*  ei  = d_in[1];
    const void*  eli = d_in[2];
    const float* ea  = (const float*)d_in[3];
    const float* W1  = (const float*)d_in[4];
    const float* b1  = (const float*)d_in[5];
    const float* W2  = (const float*)d_in[6];
    const float* b2  = (const float*)d_in[7];
    const float* Wg1 = (const float*)d_in[8];
    const float* bg1 = (const float*)d_in[9];
    const float* Wg2 = (const float*)d_in[10];
    const float* bg2 = (const float*)d_in[11];
    const float* Wp  = (const float*)d_in[12];
    const float* bp  = (const float*)d_in[13];

    float* out  = (float*)d_out;
    float* hout = out + N_LBL;

    float* h1 = (float*)sym_addr(g_h1);
    float* h  = (float*)sym_addr(g_h);
    float* xw = (float*)sym_addr(g_xw);

    // --- index preprocessing + CSR build ---
    zero_deg_kernel<<<(N_NODES + 255) / 256, 256>>>();
    detect64_kernel<<<1, 128>>>((const int*)ei, 0);
    detect64_kernel<<<1, 128>>>((const int*)eli, 1);
    convert_edges_kernel<<<(N_EDGES + 255) / 256, 256>>>(ei);
    convert_label_kernel<<<(N_LBL + 255) / 256, 256>>>(eli);
    scan_partials_kernel<<<SCAN_BLOCKS, SCAN_TPB>>>();
    scan_top_kernel<<<1, 256>>>();
    scan_final_kernel<<<SCAN_BLOCKS, SCAN_TPB>>>();
    bucket_fill_kernel<<<(N_EDGES + 255) / 256, 256>>>();

    // --- preprocess MLP ---
    {
        dim3 g(DIM_H1 / 128, (N_NODES + 127) / 128);
        gemm_kernel<128, 128, 16, 8, 8, true, true><<<g, 256>>>(x, W1, b1, h1, N_NODES, DIM_H1, DIM_IN);
    }
    {
        dim3 g(DIM_H / 64, (N_NODES + 127) / 128);
        gemm_kernel<128, 64, 16, 8, 4, true, true><<<g, 256>>>(h1, W2, b2, h, N_NODES, DIM_H, DIM_H1);
    }

    const int agg_blocks = (N_NODES + 7) / 8;   // 8 warps per block

    // --- GCN layer 1 ---
    {
        dim3 g(DIM_H / 64, (N_NODES + 127) / 128);
        gemm_kernel<128, 64, 16, 8, 4, false, false><<<g, 256>>>(h, Wg1, nullptr, xw, N_NODES, DIM_H, DIM_H);
    }
    gcn_agg_kernel<<<agg_blocks, 256>>>(xw, bg1, h);

    // --- GCN layer 2 ---
    {
        dim3 g(DIM_H / 64, (N_NODES + 127) / 128);
        gemm_kernel<128, 64, 16, 8, 4, false, false><<<g, 256>>>(h, Wg2, nullptr, xw, N_NODES, DIM_H, DIM_H);
    }
    gcn_agg_kernel<<<agg_blocks, 256>>>(xw, bg2, hout);

    // --- edge scoring head ---
    edge_score_kernel<<<(N_LBL * 32 + 255) / 256, 256>>>(hout, ea, Wp, bp, out);
}

// round 3
// speedup vs baseline: 1.4650x; 1.2049x over previous
#include <cuda_runtime.h>
#include <cstdint>
#include <cstddef>

#define N_NODES 100000
#define N_EDGES 1600000
#define N_LBL   200000
#define DIM_IN  256
#define DIM_H1  128
#define DIM_H   64
#define DIM_EA  8

#define SCAN_TPB    512
#define SCAN_BLOCKS ((N_NODES + SCAN_TPB - 1) / SCAN_TPB)   // 196

// ---------------- scratch (no allocations allowed) ----------------
__device__ __align__(16) float g_h1[(size_t)N_NODES * DIM_H1];
__device__ __align__(16) float g_h [(size_t)N_NODES * DIM_H];
__device__ __align__(16) float g_xw[(size_t)N_NODES * DIM_H];
__device__ int   g_row[N_EDGES];
__device__ int   g_col[N_EDGES];
__device__ int   g_perm[N_EDGES];       // CSR: source row per incoming edge, bucketed by col
__device__ int   g_src[N_LBL];
__device__ int   g_dst[N_LBL];
__device__ int   g_deg[N_NODES];
__device__ int   g_start[N_NODES + 1];  // CSR offsets
__device__ int   g_cursor[N_NODES];
__device__ int   g_part[SCAN_BLOCKS];
__device__ float g_dinv[N_NODES];       // rsqrt(deg+1)
__device__ float g_dinv2[N_NODES];      // 1/(deg+1)
__device__ int   g_flag[2];

__device__ __forceinline__ float leaky(float v) {
    return v > 0.0f ? v : 0.01f * v;
}

// ---------------- dtype detection ----------------
__global__ void detect64_kernel(const int* __restrict__ p, int flag_slot) {
    __shared__ int anynz;
    if (threadIdx.x == 0) anynz = 0;
    __syncthreads();
    for (int i = threadIdx.x; i < 2048; i += blockDim.x) {
        if (p[2 * i + 1] != 0) anynz = 1;
    }
    __syncthreads();
    if (threadIdx.x == 0) g_flag[flag_slot] = (anynz == 0) ? 1 : 0;
}

__global__ void zero_deg_kernel() {
    int i = blockIdx.x * blockDim.x + threadIdx.x;
    if (i < N_NODES) g_deg[i] = 0;
}

__global__ void convert_edges_kernel(const void* __restrict__ raw) {
    int e = blockIdx.x * blockDim.x + threadIdx.x;
    if (e >= N_EDGES) return;
    int r, c;
    if (g_flag[0]) {
        const long long* p = (const long long*)raw;
        r = (int)p[e];
        c = (int)p[N_EDGES + e];
    } else {
        const int* p = (const int*)raw;
        r = p[e];
        c = p[N_EDGES + e];
    }
    g_row[e] = r;
    g_col[e] = c;
    atomicAdd(&g_deg[c], 1);
}

__global__ void convert_label_kernel(const void* __restrict__ raw) {
    int e = blockIdx.x * blockDim.x + threadIdx.x;
    if (e >= N_LBL) return;
    if (g_flag[1]) {
        const long long* p = (const long long*)raw;
        g_src[e] = (int)p[e];
        g_dst[e] = (int)p[N_LBL + e];
    } else {
        const int* p = (const int*)raw;
        g_src[e] = p[e];
        g_dst[e] = p[N_LBL + e];
    }
}

// ---------------- CSR build: 3-phase prefix scan over deg ----------------
__global__ void scan_partials_kernel() {
    __shared__ int sh[SCAN_TPB];
    int t = threadIdx.x;
    int i = blockIdx.x * SCAN_TPB + t;
    int v = (i < N_NODES) ? g_deg[i] : 0;
    sh[t] = v;
    __syncthreads();
    for (int off = SCAN_TPB / 2; off > 0; off >>= 1) {
        if (t < off) sh[t] += sh[t + off];
        __syncthreads();
    }
    if (t == 0) g_part[blockIdx.x] = sh[0];
}

__global__ void scan_top_kernel() {
    __shared__ int sh[256];
    int t = threadIdx.x;
    int v = (t < SCAN_BLOCKS) ? g_part[t] : 0;
    sh[t] = v;
    __syncthreads();
    for (int off = 1; off < 256; off <<= 1) {
        int x = (t >= off) ? sh[t - off] : 0;
        __syncthreads();
        sh[t] += x;
        __syncthreads();
    }
    if (t < SCAN_BLOCKS) g_part[t] = sh[t] - v;   // exclusive
}

__global__ void scan_final_kernel() {
    __shared__ int sh[SCAN_TPB];
    int t = threadIdx.x;
    int i = blockIdx.x * SCAN_TPB + t;
    int v = (i < N_NODES) ? g_deg[i] : 0;
    sh[t] = v;
    __syncthreads();
    for (int off = 1; off < SCAN_TPB; off <<= 1) {
        int x = (t >= off) ? sh[t - off] : 0;
        __syncthreads();
        sh[t] += x;
        __syncthreads();
    }
    if (i < N_NODES) {
        int excl = g_part[blockIdx.x] + sh[t] - v;
        g_start[i]  = excl;
        g_cursor[i] = excl;
        float fd = (float)(v + 1);
        g_dinv[i]  = rsqrtf(fd);
        g_dinv2[i] = 1.0f / fd;
    }
    if (i == 0) g_start[N_NODES] = N_EDGES;
}

__global__ void bucket_fill_kernel() {
    int e = blockIdx.x * blockDim.x + threadIdx.x;
    if (e >= N_EDGES) return;
    int c = g_col[e];
    int pos = atomicAdd(&g_cursor[c], 1);
    g_perm[pos] = g_row[e];
}

// ---------------- TF32 tensor-core GEMM (3xTF32 split for fp32 accuracy) ----------------
__device__ __forceinline__ void tf32_split(float x, uint32_t& hi, uint32_t& lo) {
    uint32_t h;
    asm("cvt.rna.tf32.f32 %0, %1;" : "=r"(h) : "f"(x));
    float r = x - __uint_as_float(h);
    uint32_t l;
    asm("cvt.rna.tf32.f32 %0, %1;" : "=r"(l) : "f"(r));
    hi = h; lo = l;
}

__device__ __forceinline__ void mma_tf32(float* acc, const uint32_t* a, const uint32_t* b) {
    asm volatile(
        "mma.sync.aligned.m16n8k8.row.col.f32.tf32.tf32.f32 "
        "{%0,%1,%2,%3}, {%4,%5,%6,%7}, {%8,%9}, {%0,%1,%2,%3};"
        : "+f"(acc[0]), "+f"(acc[1]), "+f"(acc[2]), "+f"(acc[3])
        : "r"(a[0]), "r"(a[1]), "r"(a[2]), "r"(a[3]), "r"(b[0]), "r"(b[1]));
}

// C[M,N] = act(A[M,K] @ B[K,N] + bias).  BM=128, BN=64, BK=16, 256 threads (8 warps, 4x2).
// Requires: K % 16 == 0, N % 64 == 0.
template<bool BIAS, bool ACT>
__global__ __launch_bounds__(256) void tf32_gemm_kernel(
        const float* __restrict__ A, const float* __restrict__ B,
        const float* __restrict__ bias, float* __restrict__ C,
        int M, int N, int K) {
    constexpr int BM = 128, BN = 64, BK = 16;
    constexpr int ASTR = BK + 4;   // 20: conflict-free frag reads
    constexpr int BSTR = BN + 8;   // 72: conflict-free frag reads
    __shared__ float As[BM][ASTR];
    __shared__ float Bs[BK][BSTR];

    const int tid  = threadIdx.x;
    const int warp = tid >> 5, lane = tid & 31;
    const int g    = lane >> 2, tig = lane & 3;
    const int wm0  = (warp & 3) * 32;   // warp row offset in tile
    const int wn0  = (warp >> 2) * 32;  // warp col offset in tile
    const int row0 = blockIdx.y * BM;
    const int col0 = blockIdx.x * BN;

    float acc[2][4][4];
#pragma unroll
    for (int mt = 0; mt < 2; mt++)
#pragma unroll
        for (int nt = 0; nt < 4; nt++)
#pragma unroll
            for (int i = 0; i < 4; i++) acc[mt][nt][i] = 0.0f;

    for (int k0 = 0; k0 < K; k0 += BK) {
        // A: 128x16 = 512 float4, 2 per thread
#pragma unroll
        for (int i = 0; i < 2; i++) {
            int e = (tid + i * 256) * 4;
            int r = e >> 4, c = e & 15;
            float4 v = make_float4(0.f, 0.f, 0.f, 0.f);
            if (row0 + r < M)
                v = *(const float4*)(A + (size_t)(row0 + r) * K + k0 + c);
            As[r][c] = v.x; As[r][c + 1] = v.y; As[r][c + 2] = v.z; As[r][c + 3] = v.w;
        }
        // B: 16x64 = 256 float4, 1 per thread
        {
            int e = tid * 4;
            int kk = e >> 6, nn = e & 63;
            float4 v = *(const float4*)(B + (size_t)(k0 + kk) * N + col0 + nn);
            Bs[kk][nn] = v.x; Bs[kk][nn + 1] = v.y; Bs[kk][nn + 2] = v.z; Bs[kk][nn + 3] = v.w;
        }
        __syncthreads();

#pragma unroll
        for (int ks = 0; ks < BK; ks += 8) {
            uint32_t ah[2][4], al[2][4];
#pragma unroll
            for (int mt = 0; mt < 2; mt++) {
                int r = wm0 + mt * 16 + g;
                tf32_split(As[r][ks + tig],         ah[mt][0], al[mt][0]);
                tf32_split(As[r + 8][ks + tig],     ah[mt][1], al[mt][1]);
                tf32_split(As[r][ks + tig + 4],     ah[mt][2], al[mt][2]);
                tf32_split(As[r + 8][ks + tig + 4], ah[mt][3], al[mt][3]);
            }
            uint32_t bh[4][2], bl[4][2];
#pragma unroll
            for (int nt = 0; nt < 4; nt++) {
                int c = wn0 + nt * 8 + g;
                tf32_split(Bs[ks + tig][c],     bh[nt][0], bl[nt][0]);
                tf32_split(Bs[ks + tig + 4][c], bh[nt][1], bl[nt][1]);
            }
#pragma unroll
            for (int mt = 0; mt < 2; mt++)
#pragma unroll
                for (int nt = 0; nt < 4; nt++) {
                    mma_tf32(acc[mt][nt], ah[mt], bh[nt]);
                    mma_tf32(acc[mt][nt], ah[mt], bl[nt]);
                    mma_tf32(acc[mt][nt], al[mt], bh[nt]);
                }
        }
        __syncthreads();
    }

    // epilogue
#pragma unroll
    for (int mt = 0; mt < 2; mt++) {
#pragma unroll
        for (int nt = 0; nt < 4; nt++) {
            int r = row0 + wm0 + mt * 16 + g;
            int c = col0 + wn0 + nt * 8 + 2 * tig;
            float b0 = 0.f, b1 = 0.f;
            if (BIAS) { b0 = __ldg(&bias[c]); b1 = __ldg(&bias[c + 1]); }
            if (r < M) {
                float v0 = acc[mt][nt][0] + b0;
                float v1 = acc[mt][nt][1] + b1;
                if (ACT) { v0 = leaky(v0); v1 = leaky(v1); }
                *(float2*)(C + (size_t)r * N + c) = make_float2(v0, v1);
            }
            if (r + 8 < M) {
                float v2 = acc[mt][nt][2] + b0;
                float v3 = acc[mt][nt][3] + b1;
                if (ACT) { v2 = leaky(v2); v3 = leaky(v3); }
                *(float2*)(C + (size_t)(r + 8) * N + c) = make_float2(v2, v3);
            }
        }
    }
}

// ---------------- fused GCN aggregation: one warp per destination node ----------------
__global__ void gcn_agg_kernel(const float* __restrict__ xw,
                               const float* __restrict__ bias,
                               float* __restrict__ hdst) {
    int node = blockIdx.x * (blockDim.x >> 5) + (threadIdx.x >> 5);
    int lane = threadIdx.x & 31;
    if (node >= N_NODES) return;

    int s   = g_start[node];
    int end = g_start[node + 1];
    float dcol = g_dinv[node];

    float a0 = 0.0f, a1 = 0.0f;
    int j = s;
    for (; j + 2 <= end; j += 2) {
        int r0 = g_perm[j];
        int r1 = g_perm[j + 1];
        float w0 = g_dinv[r0] * dcol;
        float w1 = g_dinv[r1] * dcol;
        const float* p0 = xw + (size_t)r0 * DIM_H;
        const float* p1 = xw + (size_t)r1 * DIM_H;
        float v00 = p0[lane], v01 = p0[lane + 32];
        float v10 = p1[lane], v11 = p1[lane + 32];
        a0 = fmaf(w0, v00, a0);
        a1 = fmaf(w0, v01, a1);
        a0 = fmaf(w1, v10, a0);
        a1 = fmaf(w1, v11, a1);
    }
    if (j < end) {
        int r0 = g_perm[j];
        float w0 = g_dinv[r0] * dcol;
        const float* p0 = xw + (size_t)r0 * DIM_H;
        a0 = fmaf(w0, p0[lane], a0);
        a1 = fmaf(w0, p0[lane + 32], a1);
    }
    float sw = g_dinv2[node];
    const float* ps = xw + (size_t)node * DIM_H;
    a0 = fmaf(sw, ps[lane], a0);
    a1 = fmaf(sw, ps[lane + 32], a1);

    a0 = leaky(a0 + bias[lane]);
    a1 = leaky(a1 + bias[lane + 32]);
    float* pd = hdst + (size_t)node * DIM_H;
    pd[lane]      = a0;
    pd[lane + 32] = a1;
}

// ---------------- edge scoring head: one warp per label edge ----------------
__global__ void edge_score_kernel(const float* __restrict__ h,
                                  const float* __restrict__ ea,
                                  const float* __restrict__ Wp,
                                  const float* __restrict__ bp,
                                  float* __restrict__ out) {
    int warp = (blockIdx.x * blockDim.x + threadIdx.x) >> 5;
    int lane = threadIdx.x & 31;
    if (warp >= N_LBL) return;
    int s = g_src[warp], d = g_dst[warp];
    const float* hs = h + (size_t)s * DIM_H;
    const float* hd = h + (size_t)d * DIM_H;
    float acc = hs[lane]      * __ldg(&Wp[lane])
              + hs[lane + 32] * __ldg(&Wp[lane + 32])
              + hd[lane]      * __ldg(&Wp[64 + lane])
              + hd[lane + 32] * __ldg(&Wp[96 + lane]);
    if (lane < DIM_EA)
        acc += ea[(size_t)warp * DIM_EA + lane] * __ldg(&Wp[128 + lane]);
#pragma unroll
    for (int o = 16; o; o >>= 1) acc += __shfl_xor_sync(0xffffffffu, acc, o);
    if (lane == 0) out[warp] = acc + __ldg(&bp[0]);
}

// ---------------- host ----------------
static void* sym_addr(const void* sym) {
    void* p = nullptr;
    cudaGetSymbolAddress(&p, sym);
    return p;
}

extern "C" void kernel_launch(void* const* d_in, const int* in_sizes, int n_in,
                              void* d_out, int out_size) {
    const float* x   = (const float*)d_in[0];
    const void*  ei  = d_in[1];
    const void*  eli = d_in[2];
    const float* ea  = (const float*)d_in[3];
    const float* W1  = (const float*)d_in[4];
    const float* b1  = (const float*)d_in[5];
    const float* W2  = (const float*)d_in[6];
    const float* b2  = (const float*)d_in[7];
    const float* Wg1 = (const float*)d_in[8];
    const float* bg1 = (const float*)d_in[9];
    const float* Wg2 = (const float*)d_in[10];
    const float* bg2 = (const float*)d_in[11];
    const float* Wp  = (const float*)d_in[12];
    const float* bp  = (const float*)d_in[13];

    float* out  = (float*)d_out;
    float* hout = out + N_LBL;

    float* h1 = (float*)sym_addr(g_h1);
    float* h  = (float*)sym_addr(g_h);
    float* xw = (float*)sym_addr(g_xw);

    // --- index preprocessing + CSR build ---
    zero_deg_kernel<<<(N_NODES + 255) / 256, 256>>>();
    detect64_kernel<<<1, 128>>>((const int*)ei, 0);
    detect64_kernel<<<1, 128>>>((const int*)eli, 1);
    convert_edges_kernel<<<(N_EDGES + 255) / 256, 256>>>(ei);
    convert_label_kernel<<<(N_LBL + 255) / 256, 256>>>(eli);
    scan_partials_kernel<<<SCAN_BLOCKS, SCAN_TPB>>>();
    scan_top_kernel<<<1, 256>>>();
    scan_final_kernel<<<SCAN_BLOCKS, SCAN_TPB>>>();
    bucket_fill_kernel<<<(N_EDGES + 255) / 256, 256>>>();

    const int gy = (N_NODES + 127) / 128;

    // --- preprocess MLP ---
    tf32_gemm_kernel<true, true><<<dim3(DIM_H1 / 64, gy), 256>>>(x, W1, b1, h1, N_NODES, DIM_H1, DIM_IN);
    tf32_gemm_kernel<true, true><<<dim3(DIM_H / 64, gy), 256>>>(h1, W2, b2, h, N_NODES, DIM_H, DIM_H1);

    const int agg_blocks = (N_NODES + 7) / 8;

    // --- GCN layer 1 ---
    tf32_gemm_kernel<false, false><<<dim3(DIM_H / 64, gy), 256>>>(h, Wg1, nullptr, xw, N_NODES, DIM_H, DIM_H);
    gcn_agg_kernel<<<agg_blocks, 256>>>(xw, bg1, h);

    // --- GCN layer 2 ---
    tf32_gemm_kernel<false, false><<<dim3(DIM_H / 64, gy), 256>>>(h, Wg2, nullptr, xw, N_NODES, DIM_H, DIM_H);
    gcn_agg_kernel<<<agg_blocks, 256>>>(xw, bg2, hout);

    // --- edge scoring head ---
    edge_score_kernel<<<(N_LBL * 32 + 255) / 256, 256>>>(hout, ea, Wp, bp, out);
}